// round 4
// baseline (speedup 1.0000x reference)
#include <cuda_runtime.h>
#include <stdint.h>

// Problem constants
#define NT    4000
#define NS    16
#define NR    512
#define NCOL  (NS * NR)        // 8192 columns
#define TPB   256
#define WARPS (TPB / 32)       // 8
#define COLS_PER_BLK 32
#define GRID  (NCOL / COLS_PER_BLK)  // 256 blocks
#define TSEG  (NT / WARPS)     // 500 time samples per warp

// Self-restoring accumulator state (zero-initialized once at module load;
// the last block resets it after producing the output, so every graph
// replay starts from zero).
__device__ unsigned long long g_accum;
__device__ unsigned int       g_done;

// Single fused kernel:
//  - warp w of each block scans time slice [w*500, (w+1)*500) of 32 columns
//    (lane = column). Every warp load is one contiguous 128B line.
//  - packed argmax key: (float_bits(|v|max) << 32) | ~t  -> u64 max gives
//    larger |v|; on tie the smaller t wins (matches jnp.argmax), both within
//    a slice (strict >) and across slices (u64 max of packed keys).
//  - per-warp partials combined in smem by warp 0, exact integer MSE sum via
//    one atomicAdd per block, last block finalizes + resets state.
__global__ __launch_bounds__(TPB) void traveltime_mse_kernel(
    const float* __restrict__ x, const float* __restrict__ y,
    float* __restrict__ out)
{
    const int lane = threadIdx.x & 31;
    const int w    = threadIdx.x >> 5;
    const int col  = blockIdx.x * COLS_PER_BLK + lane;
    const int t0   = w * TSEG;

    const float* __restrict__ px = x + (size_t)t0 * NCOL + col;
    const float* __restrict__ py = y + (size_t)t0 * NCOL + col;

    float mx = -1.0f, my = -1.0f;
    int   ix = 0,     iy = 0;

    #pragma unroll 8
    for (int i = 0; i < TSEG; ++i) {
        const float vx = fabsf(px[(size_t)i * NCOL]);
        const float vy = fabsf(py[(size_t)i * NCOL]);
        const int t = t0 + i;
        if (vx > mx) ix = t;
        mx = fmaxf(vx, mx);
        if (vy > my) iy = t;
        my = fmaxf(vy, my);
    }

    __shared__ unsigned long long sx[WARPS][COLS_PER_BLK];
    __shared__ unsigned long long sy[WARPS][COLS_PER_BLK];
    sx[w][lane] = ((unsigned long long)__float_as_uint(mx) << 32)
                | (unsigned int)~ix;
    sy[w][lane] = ((unsigned long long)__float_as_uint(my) << 32)
                | (unsigned int)~iy;
    __syncthreads();

    if (w == 0) {
        unsigned long long bx = sx[0][lane];
        unsigned long long by = sy[0][lane];
        #pragma unroll
        for (int k = 1; k < WARPS; ++k) {
            unsigned long long kx = sx[k][lane];
            unsigned long long ky = sy[k][lane];
            bx = (kx > bx) ? kx : bx;
            by = (ky > by) ? ky : by;
        }

        const int tx = (int)(~(unsigned int)bx);
        const int ty = (int)(~(unsigned int)by);
        const long long d = (long long)tx - (long long)ty;
        unsigned long long sq = (unsigned long long)(d * d);

        #pragma unroll
        for (int off = 16; off > 0; off >>= 1)
            sq += __shfl_down_sync(0xffffffffu, sq, off);

        if (lane == 0) {
            atomicAdd(&g_accum, sq);
            __threadfence();
            const unsigned int ticket = atomicAdd(&g_done, 1u);
            if (ticket == (unsigned int)(GRID - 1)) {
                // Last block: all partials are in g_accum.
                const unsigned long long total = atomicAdd(&g_accum, 0ull);
                out[0] = (float)((double)total / (double)NCOL);
                // Reset for the next graph replay.
                __threadfence();
                g_accum = 0ull;
                g_done  = 0u;
            }
        }
    }
}

extern "C" void kernel_launch(void* const* d_in, const int* in_sizes, int n_in,
                              void* d_out, int out_size)
{
    const float* x = (const float*)d_in[0];
    const float* y = (const float*)d_in[1];
    float* out = (float*)d_out;

    traveltime_mse_kernel<<<GRID, TPB>>>(x, y, out);
}

// round 6
// speedup vs baseline: 1.6256x; 1.6256x over previous
#include <cuda_runtime.h>
#include <stdint.h>

// Problem constants
#define NT    4000
#define NS    16
#define NR    512
#define NCOL  (NS * NR)        // 8192 columns
#define NCG   (NCOL / 4)       // 2048 float4 column-groups
#define NSEG  80
#define SEG_LEN (NT / NSEG)    // 50
#define TPB   256
#define XBLK  (NCG / TPB)      // 8
#define FIN_BLOCKS (NCOL / TPB)  // 32

// Per-column packed argmax accumulators, updated with atomicMax (REDG.MAX.64).
// key = (float_bits(|v|max) << 32) | ~t : u64 max -> larger |v| wins; on ties
// the larger ~t (= smaller t) wins, matching jnp.argmax. keys > 0 always, so
// a zeroed accumulator is a valid identity. finalize_kernel self-resets them.
__device__ unsigned long long g_bx[NCOL];
__device__ unsigned long long g_by[NCOL];
__device__ unsigned long long g_accum;
__device__ unsigned int       g_done;

// Kernel 1: grid (XBLK, NSEG) = 640 blocks, 163,840 threads.
// Thread (cg, seg) scans SEG_LEN=50 time samples of 4 adjacent columns
// (float4) for both x and y; every warp load is 512B of contiguous lines.
__global__ __launch_bounds__(TPB) void seg_argmax_kernel(
    const float* __restrict__ x, const float* __restrict__ y)
{
    const int cg  = blockIdx.x * TPB + threadIdx.x;   // 0..NCG-1
    const int seg = blockIdx.y;                       // 0..NSEG-1
    const int t0  = seg * SEG_LEN;

    const float4* __restrict__ px = (const float4*)x + (size_t)t0 * NCG + cg;
    const float4* __restrict__ py = (const float4*)y + (size_t)t0 * NCG + cg;

    float mx0 = -1.f, mx1 = -1.f, mx2 = -1.f, mx3 = -1.f;
    float my0 = -1.f, my1 = -1.f, my2 = -1.f, my3 = -1.f;
    int ix0 = t0, ix1 = t0, ix2 = t0, ix3 = t0;
    int iy0 = t0, iy1 = t0, iy2 = t0, iy3 = t0;

    #pragma unroll 5
    for (int i = 0; i < SEG_LEN; ++i) {
        const float4 vx = px[(size_t)i * NCG];
        const float4 vy = py[(size_t)i * NCG];
        const int t = t0 + i;

        if (fabsf(vx.x) > mx0) ix0 = t; mx0 = fmaxf(fabsf(vx.x), mx0);
        if (fabsf(vx.y) > mx1) ix1 = t; mx1 = fmaxf(fabsf(vx.y), mx1);
        if (fabsf(vx.z) > mx2) ix2 = t; mx2 = fmaxf(fabsf(vx.z), mx2);
        if (fabsf(vx.w) > mx3) ix3 = t; mx3 = fmaxf(fabsf(vx.w), mx3);

        if (fabsf(vy.x) > my0) iy0 = t; my0 = fmaxf(fabsf(vy.x), my0);
        if (fabsf(vy.y) > my1) iy1 = t; my1 = fmaxf(fabsf(vy.y), my1);
        if (fabsf(vy.z) > my2) iy2 = t; my2 = fmaxf(fabsf(vy.z), my2);
        if (fabsf(vy.w) > my3) iy3 = t; my3 = fmaxf(fabsf(vy.w), my3);
    }

    const int colb = 4 * cg;
    atomicMax(&g_bx[colb + 0],
        ((unsigned long long)__float_as_uint(mx0) << 32) | (unsigned int)~ix0);
    atomicMax(&g_bx[colb + 1],
        ((unsigned long long)__float_as_uint(mx1) << 32) | (unsigned int)~ix1);
    atomicMax(&g_bx[colb + 2],
        ((unsigned long long)__float_as_uint(mx2) << 32) | (unsigned int)~ix2);
    atomicMax(&g_bx[colb + 3],
        ((unsigned long long)__float_as_uint(mx3) << 32) | (unsigned int)~ix3);
    atomicMax(&g_by[colb + 0],
        ((unsigned long long)__float_as_uint(my0) << 32) | (unsigned int)~iy0);
    atomicMax(&g_by[colb + 1],
        ((unsigned long long)__float_as_uint(my1) << 32) | (unsigned int)~iy1);
    atomicMax(&g_by[colb + 2],
        ((unsigned long long)__float_as_uint(my2) << 32) | (unsigned int)~iy2);
    atomicMax(&g_by[colb + 3],
        ((unsigned long long)__float_as_uint(my3) << 32) | (unsigned int)~iy3);
}

// Kernel 2: O(1) work per thread. Read per-column winners, self-reset them
// for the next graph replay, exact integer MSE, one atomicAdd per block,
// ticketed last block writes the output and resets the accumulator.
__global__ __launch_bounds__(TPB) void finalize_kernel(float* __restrict__ out)
{
    const int col = blockIdx.x * TPB + threadIdx.x;

    const unsigned long long bx = g_bx[col];
    const unsigned long long by = g_by[col];
    g_bx[col] = 0ull;                 // reset for next replay (own column only)
    g_by[col] = 0ull;

    const int tx = (int)(~(unsigned int)bx);
    const int ty = (int)(~(unsigned int)by);
    const long long d = (long long)tx - (long long)ty;
    unsigned long long sq = (unsigned long long)(d * d);

    #pragma unroll
    for (int off = 16; off > 0; off >>= 1)
        sq += __shfl_down_sync(0xffffffffu, sq, off);

    __shared__ unsigned long long warp_sums[TPB / 32];
    const int lane = threadIdx.x & 31;
    const int wid  = threadIdx.x >> 5;
    if (lane == 0) warp_sums[wid] = sq;
    __syncthreads();

    if (wid == 0) {
        unsigned long long v = (lane < TPB / 32) ? warp_sums[lane] : 0ull;
        #pragma unroll
        for (int off = 4; off > 0; off >>= 1)
            v += __shfl_down_sync(0xffffffffu, v, off);
        if (lane == 0) {
            atomicAdd(&g_accum, v);
            __threadfence();
            const unsigned int ticket = atomicAdd(&g_done, 1u);
            if (ticket == (unsigned int)(FIN_BLOCKS - 1)) {
                const unsigned long long total = atomicAdd(&g_accum, 0ull);
                out[0] = (float)((double)total / (double)NCOL);
                __threadfence();
                g_accum = 0ull;
                g_done  = 0u;
            }
        }
    }
}

extern "C" void kernel_launch(void* const* d_in, const int* in_sizes, int n_in,
                              void* d_out, int out_size)
{
    const float* x = (const float*)d_in[0];
    const float* y = (const float*)d_in[1];
    float* out = (float*)d_out;

    dim3 grid1(XBLK, NSEG);
    seg_argmax_kernel<<<grid1, TPB>>>(x, y);
    finalize_kernel<<<FIN_BLOCKS, TPB>>>(out);
}